// round 1
// baseline (speedup 1.0000x reference)
#include <cuda_runtime.h>
#include <math.h>

#define T_MAX 1024

// Global accumulators (scratch) — __device__ globals per the no-alloc rule.
__device__ float g_S[T_MAX];    // sum exp(risk) over rows with time==t
__device__ float g_R[T_MAX];    // sum exp(risk) over event rows with time==t
__device__ float g_TR[T_MAX];   // sum risk over event rows with time==t
__device__ int   g_D[T_MAX];    // event count per bin

__global__ void efron_init_kernel() {
    int t = blockIdx.x * blockDim.x + threadIdx.x;
    if (t < T_MAX) {
        g_S[t]  = 0.0f;
        g_R[t]  = 0.0f;
        g_TR[t] = 0.0f;
        g_D[t]  = 0;
    }
}

__global__ __launch_bounds__(512) void efron_hist_kernel(
    const int4* __restrict__ times4,
    const int4* __restrict__ events4,
    const float4* __restrict__ risk4,
    int n4)
{
    __shared__ float sS[T_MAX];
    __shared__ float sR[T_MAX];
    __shared__ float sT[T_MAX];
    __shared__ int   sD[T_MAX];

    for (int i = threadIdx.x; i < T_MAX; i += blockDim.x) {
        sS[i] = 0.0f; sR[i] = 0.0f; sT[i] = 0.0f; sD[i] = 0;
    }
    __syncthreads();

    const int stride = gridDim.x * blockDim.x;
    for (int i = blockIdx.x * blockDim.x + threadIdx.x; i < n4; i += stride) {
        int4   t = times4[i];
        int4   e = events4[i];
        float4 r = risk4[i];

        float er;

        er = __expf(r.x);
        atomicAdd(&sS[t.x], er);
        if (e.x) { atomicAdd(&sR[t.x], er); atomicAdd(&sT[t.x], r.x); atomicAdd(&sD[t.x], 1); }

        er = __expf(r.y);
        atomicAdd(&sS[t.y], er);
        if (e.y) { atomicAdd(&sR[t.y], er); atomicAdd(&sT[t.y], r.y); atomicAdd(&sD[t.y], 1); }

        er = __expf(r.z);
        atomicAdd(&sS[t.z], er);
        if (e.z) { atomicAdd(&sR[t.z], er); atomicAdd(&sT[t.z], r.z); atomicAdd(&sD[t.z], 1); }

        er = __expf(r.w);
        atomicAdd(&sS[t.w], er);
        if (e.w) { atomicAdd(&sR[t.w], er); atomicAdd(&sT[t.w], r.w); atomicAdd(&sD[t.w], 1); }
    }
    __syncthreads();

    for (int i = threadIdx.x; i < T_MAX; i += blockDim.x) {
        atomicAdd(&g_S[i],  sS[i]);
        atomicAdd(&g_R[i],  sR[i]);
        atomicAdd(&g_TR[i], sT[i]);
        atomicAdd(&g_D[i],  sD[i]);
    }
}

// Closed form for the Efron inner sum:
//   sum_{j=0}^{d-1} log(S - (j/d)*R)
//     = d*log(R/d) + lgamma(x+1) - lgamma(x-d+1),  x = S*d/R
// (exact identity; S >= R guarantees x >= d so arguments stay >= 1).
__global__ __launch_bounds__(T_MAX) void efron_finalize_kernel(float* __restrict__ out) {
    __shared__ double red[T_MAX];
    const int t = threadIdx.x;

    const float S  = g_S[t];
    const float R  = g_R[t];
    const float TR = g_TR[t];
    const int   d  = g_D[t];

    double c = 0.0;
    if (d > 0) {
        double dd = (double)d;
        double Sd = (double)S;
        double Rd = (double)R;
        double x  = Sd * dd / Rd;
        c = dd * log(Rd / dd) + lgamma(x + 1.0) - lgamma(x - dd + 1.0);
        c -= (double)TR;   // only event bins contribute tie_risk (TR==0 when d==0 anyway)
    } else {
        c = -(double)TR;   // TR is 0 here, but keep exact parity with reference
    }
    red[t] = c;
    __syncthreads();

    #pragma unroll
    for (int s = T_MAX / 2; s > 0; s >>= 1) {
        if (t < s) red[t] += red[t + s];
        __syncthreads();
    }

    if (t == 0) out[0] = (float)red[0];

    // Flattened tuple layout: [loss(1) | tie_count(1024) | cum_exp_risk(1024) | failure_time(1024)]
    out[1 + t]             = (float)d;
    out[1 + T_MAX + t]     = S;
    out[1 + 2 * T_MAX + t] = (float)t;
}

extern "C" void kernel_launch(void* const* d_in, const int* in_sizes, int n_in,
                              void* d_out, int out_size) {
    const int*   times  = (const int*)d_in[0];
    const int*   events = (const int*)d_in[1];
    const float* risk   = (const float*)d_in[2];
    float* out = (float*)d_out;

    const int n  = in_sizes[0];
    const int n4 = n / 4;   // N = 16777216, divisible by 4

    efron_init_kernel<<<(T_MAX + 255) / 256, 256>>>();

    const int blocks  = 296;   // 2 per SM
    const int threads = 512;
    efron_hist_kernel<<<blocks, threads>>>(
        (const int4*)times, (const int4*)events, (const float4*)risk, n4);

    efron_finalize_kernel<<<1, T_MAX>>>(out);

    (void)n_in; (void)out_size;
}

// round 4
// speedup vs baseline: 1.2653x; 1.2653x over previous
#include <cuda_runtime.h>
#include <math.h>

#define T_MAX 1024

// Fixed-point pack layout for the per-block shared histogram (one ull per bin):
//   bits [36:64)  S-sum  * 2^18   (sum exp(risk), all rows)       capacity ~1024.0
//   bits [ 8:36)  R-sum  * 2^18   (sum exp(risk), event rows)     capacity ~1024.0
//   bits [ 0: 8)  d      (event count)                            capacity 255
#define FP_SCALE      262144.0f          // 2^18
#define FP_INV_SCALE  3.814697265625e-6f // 2^-18

// Global accumulators — zero at module load; finalize re-zeros them each call
// so every graph replay sees a clean state (no init kernel needed).
__device__ float g_S[T_MAX];
__device__ float g_R[T_MAX];
__device__ int   g_D[T_MAX];
__device__ float g_TRtot;   // global sum of risk over event rows

__global__ __launch_bounds__(512) void efron_hist_kernel(
    const int4* __restrict__ times4,
    const int4* __restrict__ events4,
    const float4* __restrict__ risk4,
    int n4)
{
    __shared__ unsigned long long sH[T_MAX];   // packed S|R|d
    __shared__ float sWarpTR[16];

    for (int i = threadIdx.x; i < T_MAX; i += blockDim.x) sH[i] = 0ull;
    __syncthreads();

    float tr = 0.0f;
    const int stride = gridDim.x * blockDim.x;
    for (int i = blockIdx.x * blockDim.x + threadIdx.x; i < n4; i += stride) {
        int4   t = times4[i];
        int4   e = events4[i];
        float4 r = risk4[i];

        {
            unsigned int qs = (unsigned int)__fmaf_rn(__expf(r.x), FP_SCALE, 0.5f);
            unsigned long long p = ((unsigned long long)qs << 36);
            if (e.x) { p |= ((unsigned long long)qs << 8) | 1ull; tr += r.x; }
            atomicAdd(&sH[t.x], p);
        }
        {
            unsigned int qs = (unsigned int)__fmaf_rn(__expf(r.y), FP_SCALE, 0.5f);
            unsigned long long p = ((unsigned long long)qs << 36);
            if (e.y) { p |= ((unsigned long long)qs << 8) | 1ull; tr += r.y; }
            atomicAdd(&sH[t.y], p);
        }
        {
            unsigned int qs = (unsigned int)__fmaf_rn(__expf(r.z), FP_SCALE, 0.5f);
            unsigned long long p = ((unsigned long long)qs << 36);
            if (e.z) { p |= ((unsigned long long)qs << 8) | 1ull; tr += r.z; }
            atomicAdd(&sH[t.z], p);
        }
        {
            unsigned int qs = (unsigned int)__fmaf_rn(__expf(r.w), FP_SCALE, 0.5f);
            unsigned long long p = ((unsigned long long)qs << 36);
            if (e.w) { p |= ((unsigned long long)qs << 8) | 1ull; tr += r.w; }
            atomicAdd(&sH[t.w], p);
        }
    }

    // Block-reduce the tie-risk scalar.
    #pragma unroll
    for (int o = 16; o > 0; o >>= 1) tr += __shfl_xor_sync(0xFFFFFFFFu, tr, o);
    if ((threadIdx.x & 31) == 0) sWarpTR[threadIdx.x >> 5] = tr;
    __syncthreads();

    if (threadIdx.x < 16) {
        float v = sWarpTR[threadIdx.x];
        #pragma unroll
        for (int o = 8; o > 0; o >>= 1) v += __shfl_xor_sync(0xFFFFu, v, o);
        if (threadIdx.x == 0) atomicAdd(&g_TRtot, v);
    }

    // Merge the packed block histogram into global float/int accumulators.
    for (int i = threadIdx.x; i < T_MAX; i += blockDim.x) {
        unsigned long long v = sH[i];
        unsigned int d  = (unsigned int)(v & 0xFFull);
        unsigned int qr = (unsigned int)((v >> 8) & 0xFFFFFFFull);
        unsigned long long qs = v >> 36;
        atomicAdd(&g_S[i], (float)qs * FP_INV_SCALE);
        atomicAdd(&g_R[i], (float)qr * FP_INV_SCALE);
        atomicAdd(&g_D[i], (int)d);
    }
}

// Closed form for the Efron inner sum:
//   sum_{j=0}^{d-1} log(S - (j/d)*R) = d*log(R/d) + lgamma(x+1) - lgamma(x-d+1)
// with x = S*d/R  (exact identity; S >= R guarantees x >= d).
__global__ __launch_bounds__(T_MAX) void efron_finalize_kernel(float* __restrict__ out) {
    __shared__ double red[T_MAX];
    const int t = threadIdx.x;

    const float S  = g_S[t];
    const float R  = g_R[t];
    const int   d  = g_D[t];

    double c = 0.0;
    if (d > 0) {
        float df = (float)d;
        float x  = (float)((double)S * (double)d / (double)R);
        c = (double)(df * __logf(R / df) + lgammaf(x + 1.0f) - lgammaf(x - df + 1.0f));
    }
    red[t] = c;
    __syncthreads();

    #pragma unroll
    for (int s = T_MAX / 2; s > 0; s >>= 1) {
        if (t < s) red[t] += red[t + s];
        __syncthreads();
    }

    if (t == 0) {
        out[0] = (float)(red[0] - (double)g_TRtot);
        g_TRtot = 0.0f;
    }

    // Flattened tuple: [loss(1) | tie_count(1024) | cum_exp_risk(1024) | failure_time(1024)]
    out[1 + t]             = (float)d;
    out[1 + T_MAX + t]     = S;
    out[1 + 2 * T_MAX + t] = (float)t;

    // Re-zero accumulators for the next invocation / graph replay.
    g_S[t] = 0.0f;
    g_R[t] = 0.0f;
    g_D[t] = 0;
}

extern "C" void kernel_launch(void* const* d_in, const int* in_sizes, int n_in,
                              void* d_out, int out_size) {
    const int*   times  = (const int*)d_in[0];
    const int*   events = (const int*)d_in[1];
    const float* risk   = (const float*)d_in[2];
    float* out = (float*)d_out;

    const int n  = in_sizes[0];
    const int n4 = n / 4;   // N = 16777216, divisible by 4

    const int blocks  = 444;   // 3 per SM (148 SMs), 12 KB smem each
    const int threads = 512;
    efron_hist_kernel<<<blocks, threads>>>(
        (const int4*)times, (const int4*)events, (const float4*)risk, n4);

    efron_finalize_kernel<<<1, T_MAX>>>(out);

    (void)n_in; (void)out_size;
}

// round 5
// speedup vs baseline: 1.3446x; 1.0627x over previous
#include <cuda_runtime.h>
#include <math.h>

#define T_MAX 1024

// Packed event-row accumulator (one ull per bin):
//   bits [36:64)  S-contribution of EVENT rows * 2^18   capacity ~1024.0
//   bits [ 8:36)  R-sum * 2^18                           capacity ~1024.0
//   bits [ 0: 8)  d (event count)                        capacity 255
#define FP_SCALE      262144.0f          // 2^18
#define FP_INV_SCALE  3.814697265625e-6f // 2^-18

// Device-global scratch — zero at load; finalize re-zeros for graph replay.
__device__ float  g_S[T_MAX];
__device__ float  g_R[T_MAX];
__device__ int    g_D[T_MAX];
__device__ float  g_TRtot;
__device__ double g_loss;

__global__ __launch_bounds__(512) void efron_hist_kernel(
    const int4* __restrict__ times4,
    const int4* __restrict__ events4,
    const float4* __restrict__ risk4,
    int n4)
{
    __shared__ float              sSf[T_MAX];  // S from non-event rows (float)
    __shared__ unsigned long long sH[T_MAX];   // packed S|R|d from event rows
    __shared__ float              sWarpTR[16];

    for (int i = threadIdx.x; i < T_MAX; i += blockDim.x) { sSf[i] = 0.0f; sH[i] = 0ull; }
    __syncthreads();

    float tr = 0.0f;
    const int stride = gridDim.x * blockDim.x;
    for (int i = blockIdx.x * blockDim.x + threadIdx.x; i < n4; i += stride) {
        int4   t = times4[i];
        int4   e = events4[i];
        float4 r = risk4[i];

        {
            float er = __expf(r.x);
            if (e.x) {
                unsigned long long qs = (unsigned long long)(unsigned int)__fmaf_rn(er, FP_SCALE, 0.5f);
                atomicAdd(&sH[t.x], (qs << 36) | (qs << 8) | 1ull);
                tr += r.x;
            } else {
                atomicAdd(&sSf[t.x], er);
            }
        }
        {
            float er = __expf(r.y);
            if (e.y) {
                unsigned long long qs = (unsigned long long)(unsigned int)__fmaf_rn(er, FP_SCALE, 0.5f);
                atomicAdd(&sH[t.y], (qs << 36) | (qs << 8) | 1ull);
                tr += r.y;
            } else {
                atomicAdd(&sSf[t.y], er);
            }
        }
        {
            float er = __expf(r.z);
            if (e.z) {
                unsigned long long qs = (unsigned long long)(unsigned int)__fmaf_rn(er, FP_SCALE, 0.5f);
                atomicAdd(&sH[t.z], (qs << 36) | (qs << 8) | 1ull);
                tr += r.z;
            } else {
                atomicAdd(&sSf[t.z], er);
            }
        }
        {
            float er = __expf(r.w);
            if (e.w) {
                unsigned long long qs = (unsigned long long)(unsigned int)__fmaf_rn(er, FP_SCALE, 0.5f);
                atomicAdd(&sH[t.w], (qs << 36) | (qs << 8) | 1ull);
                tr += r.w;
            } else {
                atomicAdd(&sSf[t.w], er);
            }
        }
    }

    // Block-reduce the tie-risk scalar.
    #pragma unroll
    for (int o = 16; o > 0; o >>= 1) tr += __shfl_xor_sync(0xFFFFFFFFu, tr, o);
    if ((threadIdx.x & 31) == 0) sWarpTR[threadIdx.x >> 5] = tr;
    __syncthreads();

    if (threadIdx.x < 16) {
        float v = sWarpTR[threadIdx.x];
        #pragma unroll
        for (int o = 8; o > 0; o >>= 1) v += __shfl_xor_sync(0xFFFFu, v, o);
        if (threadIdx.x == 0) atomicAdd(&g_TRtot, v);
    }

    // Merge block histograms into global accumulators.
    for (int i = threadIdx.x; i < T_MAX; i += blockDim.x) {
        unsigned long long v = sH[i];
        unsigned int d  = (unsigned int)(v & 0xFFull);
        unsigned int qr = (unsigned int)((v >> 8) & 0xFFFFFFFull);
        float sEv = (float)(v >> 36) * FP_INV_SCALE;
        atomicAdd(&g_S[i], sSf[i] + sEv);
        atomicAdd(&g_R[i], (float)qr * FP_INV_SCALE);
        atomicAdd(&g_D[i], (int)d);
    }
}

// Closed form for the Efron inner sum:
//   sum_{j=0}^{d-1} log(S - (j/d)*R) = d*log(R/d) + lgamma(x+1) - lgamma(x-d+1)
// with x = S*d/R  (S >= R guarantees x >= d, args stay >= 1).
__global__ __launch_bounds__(128) void efron_finalize_bins(float* __restrict__ out) {
    __shared__ double sWarp[4];
    const int t = blockIdx.x * 128 + threadIdx.x;

    const float S = g_S[t];
    const float R = g_R[t];
    const int   d = g_D[t];

    double c = 0.0;
    if (d > 0) {
        float df = (float)d;
        float x  = (float)((double)S * (double)d / (double)R);
        c = (double)(df * __logf(R / df) + lgammaf(x + 1.0f) - lgammaf(x - df + 1.0f));
    }

    // Block reduce (4 warps).
    #pragma unroll
    for (int o = 16; o > 0; o >>= 1) c += __shfl_xor_sync(0xFFFFFFFFu, c, o);
    if ((threadIdx.x & 31) == 0) sWarp[threadIdx.x >> 5] = c;
    __syncthreads();
    if (threadIdx.x == 0)
        atomicAdd(&g_loss, sWarp[0] + sWarp[1] + sWarp[2] + sWarp[3]);

    // Flattened tuple: [loss(1) | tie_count(1024) | cum_exp_risk(1024) | failure_time(1024)]
    out[1 + t]             = (float)d;
    out[1 + T_MAX + t]     = S;
    out[1 + 2 * T_MAX + t] = (float)t;

    // Re-zero bin accumulators for the next graph replay.
    g_S[t] = 0.0f;
    g_R[t] = 0.0f;
    g_D[t] = 0;
}

__global__ void efron_finalize_write(float* __restrict__ out) {
    out[0] = (float)(g_loss - (double)g_TRtot);
    g_loss  = 0.0;
    g_TRtot = 0.0f;
}

extern "C" void kernel_launch(void* const* d_in, const int* in_sizes, int n_in,
                              void* d_out, int out_size) {
    const int*   times  = (const int*)d_in[0];
    const int*   events = (const int*)d_in[1];
    const float* risk   = (const float*)d_in[2];
    float* out = (float*)d_out;

    const int n  = in_sizes[0];
    const int n4 = n / 4;   // N = 16777216, divisible by 4

    efron_hist_kernel<<<444, 512>>>(
        (const int4*)times, (const int4*)events, (const float4*)risk, n4);

    efron_finalize_bins<<<T_MAX / 128, 128>>>(out);
    efron_finalize_write<<<1, 1>>>(out);

    (void)n_in; (void)out_size;
}

// round 6
// speedup vs baseline: 1.8682x; 1.3894x over previous
#include <cuda_runtime.h>
#include <math.h>

#define T_MAX 1024
#define NBLK  592     // 4 CTAs/SM on 148 SMs

// Event-row pack (32-bit, per-block shared):  bits[8:32) = R*2^12 , bits[0:8) = d
#define FP_SCALE      4096.0f
#define FP_INV_SCALE  2.44140625e-4f   // 2^-12

// Global scratch — zero at load; finalize re-zeros for graph replay.
__device__ float              g_S[T_MAX];   // non-event S sums
__device__ unsigned long long g_E[T_MAX];   // packed: qsum(R*2^12) << 16 | d
__device__ float              g_TRtot;
__device__ double             g_loss;
__device__ unsigned           g_ticket;

__global__ __launch_bounds__(512, 4) void efron_hist_kernel(
    const int4* __restrict__ times4,
    const int4* __restrict__ events4,
    const float4* __restrict__ risk4,
    int n4)
{
    __shared__ float    sS[T_MAX];   // S from non-event rows
    __shared__ unsigned sE[T_MAX];   // packed event rows (full 32-bank spread)
    __shared__ float    sWarpTR[16];

    for (int i = threadIdx.x; i < T_MAX; i += 512) { sS[i] = 0.0f; sE[i] = 0u; }
    __syncthreads();

    float tr = 0.0f;
    const int stride = gridDim.x * 512;
    for (int i = blockIdx.x * 512 + threadIdx.x; i < n4; i += stride) {
        int4   t = times4[i];
        int4   e = events4[i];
        float4 r = risk4[i];

        {
            float er = __expf(r.x);
            if (e.x) { atomicAdd(&sE[t.x], ((unsigned)__fmaf_rn(er, FP_SCALE, 0.5f) << 8) | 1u); tr += r.x; }
            else       atomicAdd(&sS[t.x], er);
        }
        {
            float er = __expf(r.y);
            if (e.y) { atomicAdd(&sE[t.y], ((unsigned)__fmaf_rn(er, FP_SCALE, 0.5f) << 8) | 1u); tr += r.y; }
            else       atomicAdd(&sS[t.y], er);
        }
        {
            float er = __expf(r.z);
            if (e.z) { atomicAdd(&sE[t.z], ((unsigned)__fmaf_rn(er, FP_SCALE, 0.5f) << 8) | 1u); tr += r.z; }
            else       atomicAdd(&sS[t.z], er);
        }
        {
            float er = __expf(r.w);
            if (e.w) { atomicAdd(&sE[t.w], ((unsigned)__fmaf_rn(er, FP_SCALE, 0.5f) << 8) | 1u); tr += r.w; }
            else       atomicAdd(&sS[t.w], er);
        }
    }

    // Block-reduce the tie-risk scalar.
    #pragma unroll
    for (int o = 16; o > 0; o >>= 1) tr += __shfl_xor_sync(0xFFFFFFFFu, tr, o);
    if ((threadIdx.x & 31) == 0) sWarpTR[threadIdx.x >> 5] = tr;
    __syncthreads();
    if (threadIdx.x < 16) {
        float v = sWarpTR[threadIdx.x];
        #pragma unroll
        for (int o = 8; o > 0; o >>= 1) v += __shfl_xor_sync(0xFFFFu, v, o);
        if (threadIdx.x == 0) atomicAdd(&g_TRtot, v);
    }

    // Merge: 2 global atomics per bin per block.
    for (int i = threadIdx.x; i < T_MAX; i += 512) {
        unsigned p = sE[i];
        atomicAdd(&g_S[i], sS[i]);
        atomicAdd(&g_E[i], ((unsigned long long)(p >> 8) << 16) | (unsigned long long)(p & 0xFFu));
    }
}

// Closed form for the Efron inner sum:
//   sum_{j=0}^{d-1} log(S - (j/d)*R) = d*log(R/d) + lgamma(x+1) - lgamma(x-d+1)
// with x = S*d/R  (S >= R guarantees x >= d; args stay >= 1).
__global__ __launch_bounds__(32) void efron_finalize_kernel(float* __restrict__ out) {
    const int t = blockIdx.x * 32 + threadIdx.x;   // 32 blocks x 32 threads = 1024 bins

    const float             Snev = g_S[t];
    const unsigned long long ev  = g_E[t];
    const int   d = (int)(ev & 0xFFFFull);
    const float R = (float)(ev >> 16) * FP_INV_SCALE;
    const float S = Snev + R;

    double c = 0.0;
    if (d > 0) {
        float df = (float)d;
        float x  = (float)((double)S * (double)d / (double)R);
        c = (double)(df * __logf(R / df) + lgammaf(x + 1.0f) - lgammaf(x - df + 1.0f));
    }

    // Flattened tuple: [loss(1) | tie_count(1024) | cum_exp_risk(1024) | failure_time(1024)]
    out[1 + t]             = (float)d;
    out[1 + T_MAX + t]     = S;
    out[1 + 2 * T_MAX + t] = (float)t;

    // Re-zero bin accumulators for the next graph replay.
    g_S[t] = 0.0f;
    g_E[t] = 0ull;

    // Warp-reduce the loss contribution, then ticket: last block writes out[0].
    #pragma unroll
    for (int o = 16; o > 0; o >>= 1) c += __shfl_xor_sync(0xFFFFFFFFu, c, o);

    if (threadIdx.x == 0) {
        atomicAdd(&g_loss, c);
        __threadfence();
        unsigned tk = atomicAdd(&g_ticket, 1u);
        if (tk == gridDim.x - 1) {
            double total = atomicAdd(&g_loss, 0.0);   // fenced read
            out[0] = (float)(total - (double)g_TRtot);
            g_loss   = 0.0;
            g_TRtot  = 0.0f;
            g_ticket = 0u;
        }
    }
}

extern "C" void kernel_launch(void* const* d_in, const int* in_sizes, int n_in,
                              void* d_out, int out_size) {
    const int*   times  = (const int*)d_in[0];
    const int*   events = (const int*)d_in[1];
    const float* risk   = (const float*)d_in[2];
    float* out = (float*)d_out;

    const int n  = in_sizes[0];
    const int n4 = n / 4;   // N = 16777216, divisible by 4

    efron_hist_kernel<<<NBLK, 512>>>(
        (const int4*)times, (const int4*)events, (const float4*)risk, n4);

    efron_finalize_kernel<<<T_MAX / 32, 32>>>(out);

    (void)n_in; (void)out_size;
}